// round 1
// baseline (speedup 1.0000x reference)
#include <cuda_runtime.h>
#include <math.h>

// Problem constants (structural)
#define NHR_MAX 100000
#define F_IN 256
#define F_W 512
#define IN_MSG 1024
#define LN_EPS 1e-5f

// Scratch (no cudaMalloc allowed): msg [M,1024], two ping-pong h buffers [M,512]
__device__ float g_msg[(size_t)NHR_MAX * IN_MSG];
__device__ float g_h0[(size_t)NHR_MAX * F_W];
__device__ float g_h1[(size_t)NHR_MAX * F_W];
__device__ int   g_idx_is64;

// ---------------------------------------------------------------------------
// idx dtype detection: jnp.int64 under default JAX becomes int32, but if the
// bench env enables x64 it stays int64. int64 LE with values < 25000 has all
// odd int32 words == 0; int32 random indices essentially never do.
// ---------------------------------------------------------------------------
__global__ void detect_idx_kernel(const int* __restrict__ idx32) {
    int allzero = 1;
    for (int i = 1; i < 128; i += 2) {
        if (idx32[i] != 0) { allzero = 0; break; }
    }
    g_idx_is64 = allzero;
}

// ---------------------------------------------------------------------------
// Prep: msg = [e_enc(512) | v[idx](256) | v_skip(256)], then LayerNorm(1024)
// One block (256 threads) per row; 4 elements per thread.
// ---------------------------------------------------------------------------
__global__ void __launch_bounds__(256)
prep_kernel(const float* __restrict__ v,
            const float* __restrict__ e_rel,
            const void*  __restrict__ idx_raw,
            const float* __restrict__ v_skip,
            const float* __restrict__ We,
            const float* __restrict__ be,
            const float* __restrict__ ln_g,
            const float* __restrict__ ln_b,
            int M) {
    int row = blockIdx.x;
    if (row >= M) return;
    int tid = threadIdx.x;

    long long src;
    if (g_idx_is64) src = ((const long long*)idx_raw)[row];
    else            src = (long long)(((const int*)idx_raw)[row]);

    float er = e_rel[row];

    float vals[4];
#pragma unroll
    for (int t = 0; t < 4; t++) {
        int j = tid + t * 256;
        float x;
        if (j < F_W) {
            x = fmaf(-er, We[j], be[j]);                 // edge encoder
        } else if (j < F_W + F_IN) {
            x = v[src * F_IN + (j - F_W)];               // gathered low-res
        } else {
            x = v_skip[(size_t)row * F_IN + (j - F_W - F_IN)];  // skip feats
        }
        vals[t] = x;
    }

    // block reduction of sum and sumsq over 1024 values
    float s  = vals[0] + vals[1] + vals[2] + vals[3];
    float s2 = vals[0]*vals[0] + vals[1]*vals[1] + vals[2]*vals[2] + vals[3]*vals[3];
#pragma unroll
    for (int o = 16; o > 0; o >>= 1) {
        s  += __shfl_xor_sync(0xFFFFFFFFu, s,  o);
        s2 += __shfl_xor_sync(0xFFFFFFFFu, s2, o);
    }
    __shared__ float red_s[8], red_s2[8];
    if ((tid & 31) == 0) { red_s[tid >> 5] = s; red_s2[tid >> 5] = s2; }
    __syncthreads();
    float sum = 0.f, sumsq = 0.f;
#pragma unroll
    for (int i = 0; i < 8; i++) { sum += red_s[i]; sumsq += red_s2[i]; }

    float mu   = sum * (1.0f / IN_MSG);
    float var  = sumsq * (1.0f / IN_MSG) - mu * mu;
    float rstd = rsqrtf(var + LN_EPS);

    float* out = g_msg + (size_t)row * IN_MSG;
#pragma unroll
    for (int t = 0; t < 4; t++) {
        int j = tid + t * 256;
        out[j] = fmaf((vals[t] - mu) * rstd, ln_g[j], ln_b[j]);
    }
}

// ---------------------------------------------------------------------------
// SELU
// ---------------------------------------------------------------------------
__device__ __forceinline__ float selu_f(float x) {
    const float sc = 1.0507009873554805f;
    const float al = 1.6732632423543772f;
    return x > 0.f ? sc * x : sc * al * expm1f(x);
}

// ---------------------------------------------------------------------------
// C[M, 512] = selu(A[M, K] @ W[512, K]^T + bias)
// Classic 128x128x8 tile, 256 threads, 8x8 per-thread microtile, float4 I/O.
// ---------------------------------------------------------------------------
__global__ void __launch_bounds__(256, 2)
gemm_bias_selu(const float* __restrict__ A,
               const float* __restrict__ W,
               const float* __restrict__ bias,
               float* __restrict__ C,
               int M, int K) {
    __shared__ float sA[8][128];
    __shared__ float sB[8][128];

    int tid = threadIdx.x;
    int bm = blockIdx.y * 128;
    int bn = blockIdx.x * 128;

    int la_r = tid >> 1;            // 0..127
    int la_c = (tid & 1) << 2;      // 0 or 4

    int tx = tid & 15;              // col group (8 cols each)
    int ty = tid >> 4;              // row group (8 rows each)

    const float* Aptr = A + (size_t)(bm + la_r) * K + la_c;
    const float* Wptr = W + (size_t)(bn + la_r) * K + la_c;
    bool a_valid = (bm + la_r) < M;

    float acc[8][8];
#pragma unroll
    for (int i = 0; i < 8; i++)
#pragma unroll
        for (int j = 0; j < 8; j++) acc[i][j] = 0.f;

    for (int k0 = 0; k0 < K; k0 += 8) {
        float4 av = a_valid ? *(const float4*)(Aptr + k0)
                            : make_float4(0.f, 0.f, 0.f, 0.f);
        float4 wv = *(const float4*)(Wptr + k0);
        sA[la_c + 0][la_r] = av.x; sA[la_c + 1][la_r] = av.y;
        sA[la_c + 2][la_r] = av.z; sA[la_c + 3][la_r] = av.w;
        sB[la_c + 0][la_r] = wv.x; sB[la_c + 1][la_r] = wv.y;
        sB[la_c + 2][la_r] = wv.z; sB[la_c + 3][la_r] = wv.w;
        __syncthreads();

#pragma unroll
        for (int kk = 0; kk < 8; kk++) {
            float a[8], b[8];
            *(float4*)&a[0] = *(const float4*)&sA[kk][ty * 8];
            *(float4*)&a[4] = *(const float4*)&sA[kk][ty * 8 + 4];
            *(float4*)&b[0] = *(const float4*)&sB[kk][tx * 8];
            *(float4*)&b[4] = *(const float4*)&sB[kk][tx * 8 + 4];
#pragma unroll
            for (int i = 0; i < 8; i++)
#pragma unroll
                for (int j = 0; j < 8; j++)
                    acc[i][j] = fmaf(a[i], b[j], acc[i][j]);
        }
        __syncthreads();
    }

    float bz[8];
    *(float4*)&bz[0] = *(const float4*)&bias[bn + tx * 8];
    *(float4*)&bz[4] = *(const float4*)&bias[bn + tx * 8 + 4];

#pragma unroll
    for (int i = 0; i < 8; i++) {
        int row = bm + ty * 8 + i;
        if (row < M) {
            float out[8];
#pragma unroll
            for (int j = 0; j < 8; j++) out[j] = selu_f(acc[i][j] + bz[j]);
            float* cp = C + (size_t)row * F_W + bn + tx * 8;
            *(float4*)&cp[0] = *(float4*)&out[0];
            *(float4*)&cp[4] = *(float4*)&out[4];
        }
    }
}

// ---------------------------------------------------------------------------
// Launch
// ---------------------------------------------------------------------------
extern "C" void kernel_launch(void* const* d_in, const int* in_sizes, int n_in,
                              void* d_out, int out_size) {
    const float* v      = (const float*)d_in[0];
    const float* e_rel  = (const float*)d_in[1];
    const void*  idx    = (const void*) d_in[2];
    const float* v_skip = (const float*)d_in[3];
    const float* We     = (const float*)d_in[4];
    const float* be     = (const float*)d_in[5];
    const float* ln_g   = (const float*)d_in[6];
    const float* ln_b   = (const float*)d_in[7];
    const float* W0     = (const float*)d_in[8];
    const float* b0     = (const float*)d_in[9];
    const float* W1     = (const float*)d_in[10];
    const float* b1     = (const float*)d_in[11];
    const float* W2     = (const float*)d_in[12];
    const float* b2     = (const float*)d_in[13];
    const float* W3     = (const float*)d_in[14];
    const float* b3     = (const float*)d_in[15];

    int M = in_sizes[1];  // e_rel has N_HR elements

    float *msg, *h0, *h1;
    cudaGetSymbolAddress((void**)&msg, g_msg);
    cudaGetSymbolAddress((void**)&h0,  g_h0);
    cudaGetSymbolAddress((void**)&h1,  g_h1);

    detect_idx_kernel<<<1, 1>>>((const int*)idx);
    prep_kernel<<<M, 256>>>(v, e_rel, idx, v_skip, We, be, ln_g, ln_b, M);

    dim3 grid(F_W / 128, (M + 127) / 128);
    gemm_bias_selu<<<grid, 256>>>(msg, W0, b0, h0, M, IN_MSG);
    gemm_bias_selu<<<grid, 256>>>(h0,  W1, b1, h1, M, F_W);
    gemm_bias_selu<<<grid, 256>>>(h1,  W2, b2, h0, M, F_W);
    gemm_bias_selu<<<grid, 256>>>(h0,  W3, b3, (float*)d_out, M, F_W);
}

// round 3
// speedup vs baseline: 1.9784x; 1.9784x over previous
#include <cuda_runtime.h>
#include <math.h>
#include <stdint.h>

// ---------------- problem constants ----------------
#define NHR_MAX 100000
#define F_IN 256
#define F_W 512
#define IN_MSG 1024
#define LN_EPS 1e-5f

// scratch (no cudaMalloc allowed)
__device__ float g_msg[(size_t)NHR_MAX * IN_MSG];
__device__ float g_h0[(size_t)NHR_MAX * F_W];
__device__ float g_h1[(size_t)NHR_MAX * F_W];
__device__ int   g_idx_is64;

// ---------------- helpers ----------------
__device__ __forceinline__ uint32_t smem_u32(const void* p) {
    uint32_t a;
    asm("{ .reg .u64 t; cvta.to.shared.u64 t, %1; cvt.u32.u64 %0, t; }" : "=r"(a) : "l"(p));
    return a;
}
__device__ __forceinline__ float selu_f(float x) {
    const float sc = 1.0507009873554805f;
    const float al = 1.6732632423543772f;
    return x > 0.f ? sc * x : sc * al * expm1f(x);
}
// pack two floats to bf16x2 (rn): result = {hi16: b, lo16: a}
__device__ __forceinline__ uint32_t bf16x2_rn(float a, float b) {
    uint32_t r;
    asm("cvt.rn.bf16x2.f32 %0, %1, %2;" : "=r"(r) : "f"(b), "f"(a));
    return r;
}
__device__ __forceinline__ float bf16lo_to_f(uint32_t p) { return __uint_as_float(p << 16); }
__device__ __forceinline__ float bf16hi_to_f(uint32_t p) { return __uint_as_float(p & 0xFFFF0000u); }

__device__ __forceinline__ void ldmatrix_x4(uint32_t& r0, uint32_t& r1, uint32_t& r2, uint32_t& r3,
                                            uint32_t addr) {
    asm volatile("ldmatrix.sync.aligned.m8n8.x4.shared.b16 {%0,%1,%2,%3}, [%4];"
                 : "=r"(r0), "=r"(r1), "=r"(r2), "=r"(r3) : "r"(addr));
}
__device__ __forceinline__ void mma_bf16(float* d, const uint32_t* a, const uint32_t* b) {
    asm volatile(
        "mma.sync.aligned.m16n8k16.row.col.f32.bf16.bf16.f32 "
        "{%0,%1,%2,%3}, {%4,%5,%6,%7}, {%8,%9}, {%0,%1,%2,%3};"
        : "+f"(d[0]), "+f"(d[1]), "+f"(d[2]), "+f"(d[3])
        : "r"(a[0]), "r"(a[1]), "r"(a[2]), "r"(a[3]), "r"(b[0]), "r"(b[1]));
}

// ---------------- idx dtype detection ----------------
__global__ void detect_idx_kernel(const int* __restrict__ idx32) {
    int allzero = 1;
    for (int i = 1; i < 128; i += 2)
        if (idx32[i] != 0) { allzero = 0; break; }
    g_idx_is64 = allzero;
}

// ---------------- prep: edge-enc | gather | skip, then LayerNorm ----------------
__global__ void __launch_bounds__(256)
prep_kernel(const float* __restrict__ v,
            const float* __restrict__ e_rel,
            const void*  __restrict__ idx_raw,
            const float* __restrict__ v_skip,
            const float* __restrict__ We,
            const float* __restrict__ be,
            const float* __restrict__ ln_g,
            const float* __restrict__ ln_b,
            int M) {
    int row = blockIdx.x;
    if (row >= M) return;
    int tid = threadIdx.x;

    long long src;
    if (g_idx_is64) src = ((const long long*)idx_raw)[row];
    else            src = (long long)(((const int*)idx_raw)[row]);

    float er = e_rel[row];

    float vals[4];
#pragma unroll
    for (int t = 0; t < 4; t++) {
        int j = tid + t * 256;
        float x;
        if (j < F_W)                 x = fmaf(-er, We[j], be[j]);
        else if (j < F_W + F_IN)     x = v[src * F_IN + (j - F_W)];
        else                         x = v_skip[(size_t)row * F_IN + (j - F_W - F_IN)];
        vals[t] = x;
    }

    float s  = vals[0] + vals[1] + vals[2] + vals[3];
    float s2 = vals[0]*vals[0] + vals[1]*vals[1] + vals[2]*vals[2] + vals[3]*vals[3];
#pragma unroll
    for (int o = 16; o > 0; o >>= 1) {
        s  += __shfl_xor_sync(0xFFFFFFFFu, s,  o);
        s2 += __shfl_xor_sync(0xFFFFFFFFu, s2, o);
    }
    __shared__ float red_s[8], red_s2[8];
    if ((tid & 31) == 0) { red_s[tid >> 5] = s; red_s2[tid >> 5] = s2; }
    __syncthreads();
    float sum = 0.f, sumsq = 0.f;
#pragma unroll
    for (int i = 0; i < 8; i++) { sum += red_s[i]; sumsq += red_s2[i]; }

    float mu   = sum * (1.0f / IN_MSG);
    float var  = sumsq * (1.0f / IN_MSG) - mu * mu;
    float rstd = rsqrtf(var + LN_EPS);

    float* out = g_msg + (size_t)row * IN_MSG;
#pragma unroll
    for (int t = 0; t < 4; t++) {
        int j = tid + t * 256;
        out[j] = fmaf((vals[t] - mu) * rstd, ln_g[j], ln_b[j]);
    }
}

// ---------------- bf16 split-precision GEMM via mma.sync ----------------
// C[M, 512] = selu(A[M,K] @ W[512,K]^T + bias)
// CTA tile 128x128, BK=32; 8 warps as 4(m) x 2(n); warp tile 32(m) x 64(n).
#define BM 128
#define BN 128
#define BK 32

// SMEM tile layout: bf16, row pitch 80 bytes (40 halves) for conflict-free ldmatrix
#define PITCH 80
#define T_A_HI 0
#define T_A_LO 10240
#define T_B_HI 20480
#define T_B_LO 30720
#define STAGE_B 40960
#define GEMM_SMEM (2 * STAGE_B)

__global__ void __launch_bounds__(256)
gemm_bf16x3_selu(const float* __restrict__ A,
                 const float* __restrict__ W,
                 const float* __restrict__ bias,
                 float* __restrict__ C,
                 int M, int K) {
    extern __shared__ char smem[];
    uint32_t sb = smem_u32(smem);

    int tid = threadIdx.x;
    int wid = tid >> 5, lid = tid & 31;
    int warp_m = wid & 3;          // 0..3 -> 32 rows each
    int warp_n = wid >> 2;         // 0..1 -> 64 cols each
    int bm = blockIdx.y * BM;
    int bn = blockIdx.x * BN;

    // global load mapping: thread covers (row = tid/2, k = (tid&1)*16 .. +15)
    int g_row  = tid >> 1;
    int g_kb   = (tid & 1) << 4;
    bool a_valid = (bm + g_row) < M;
    const float* a_src = A + (size_t)(bm + g_row) * K + g_kb;
    const float* b_src = W + (size_t)(bn + g_row) * K + g_kb;
    uint32_t sts_off = (uint32_t)(g_row * PITCH + g_kb * 2);

    float acc[2][8][4];
#pragma unroll
    for (int i = 0; i < 2; i++)
#pragma unroll
        for (int j = 0; j < 8; j++)
#pragma unroll
            for (int q = 0; q < 4; q++) acc[i][j][q] = 0.f;

    // ldmatrix base addresses (lane-dependent parts)
    // A: lanes 0-7: (m0-7, chunk0), 8-15: (m8-15, chunk0), 16-23: (m0-7, chunk1), 24-31: (m8-15, chunk1)
    int a_lrow = warp_m * 32 + (lid & 15);
    int a_lchk = (lid >> 4) * 16;                 // byte offset of k-chunk
    uint32_t a_lm_off = (uint32_t)(a_lrow * PITCH + a_lchk);
    // B: lanes 0-7: (n0-7, chunk0), 8-15: (n0-7, chunk1), 16-23: (n8-15, chunk0), 24-31: (n8-15, chunk1)
    int b_lrow = warp_n * 64 + (lid & 7) + ((lid >> 4) << 3);
    int b_lchk = ((lid >> 3) & 1) * 16;
    uint32_t b_lm_off = (uint32_t)(b_lrow * PITCH + b_lchk);

    const int S = K / BK;
    float4 av[4], bv[4];

    // prologue: load + convert + store stage 0
#pragma unroll
    for (int q = 0; q < 4; q++) {
        av[q] = a_valid ? *(const float4*)(a_src + q * 4) : make_float4(0.f, 0.f, 0.f, 0.f);
        bv[q] = *(const float4*)(b_src + q * 4);
    }
    {
        char* stg = smem;
#pragma unroll
        for (int q = 0; q < 4; q++) {
            uint32_t h0 = bf16x2_rn(av[q].x, av[q].y);
            uint32_t h1 = bf16x2_rn(av[q].z, av[q].w);
            uint32_t l0 = bf16x2_rn(av[q].x - bf16lo_to_f(h0), av[q].y - bf16hi_to_f(h0));
            uint32_t l1 = bf16x2_rn(av[q].z - bf16lo_to_f(h1), av[q].w - bf16hi_to_f(h1));
            *(uint2*)(stg + T_A_HI + sts_off + q * 8) = make_uint2(h0, h1);
            *(uint2*)(stg + T_A_LO + sts_off + q * 8) = make_uint2(l0, l1);
            uint32_t g0 = bf16x2_rn(bv[q].x, bv[q].y);
            uint32_t g1 = bf16x2_rn(bv[q].z, bv[q].w);
            uint32_t m0 = bf16x2_rn(bv[q].x - bf16lo_to_f(g0), bv[q].y - bf16hi_to_f(g0));
            uint32_t m1 = bf16x2_rn(bv[q].z - bf16lo_to_f(g1), bv[q].w - bf16hi_to_f(g1));
            *(uint2*)(stg + T_B_HI + sts_off + q * 8) = make_uint2(g0, g1);
            *(uint2*)(stg + T_B_LO + sts_off + q * 8) = make_uint2(m0, m1);
        }
    }
    __syncthreads();

    for (int s = 0; s < S; s++) {
        int cur = s & 1;
        uint32_t tile = sb + cur * STAGE_B;

        // prefetch next stage to regs
        if (s + 1 < S) {
            int k0 = (s + 1) * BK;
#pragma unroll
            for (int q = 0; q < 4; q++) {
                av[q] = a_valid ? *(const float4*)(a_src + k0 + q * 4)
                                : make_float4(0.f, 0.f, 0.f, 0.f);
                bv[q] = *(const float4*)(b_src + k0 + q * 4);
            }
        }

        // compute over current stage: 2 k16 steps
#pragma unroll
        for (int kk = 0; kk < 2; kk++) {
            uint32_t koff = kk * 32;  // 16 halves = 32 bytes
            uint32_t ahi[2][4], alo[2][4];
#pragma unroll
            for (int mf = 0; mf < 2; mf++) {
                uint32_t ad = tile + T_A_HI + a_lm_off + mf * (16 * PITCH) + koff;
                ldmatrix_x4(ahi[mf][0], ahi[mf][1], ahi[mf][2], ahi[mf][3], ad);
                ad = tile + T_A_LO + a_lm_off + mf * (16 * PITCH) + koff;
                ldmatrix_x4(alo[mf][0], alo[mf][1], alo[mf][2], alo[mf][3], ad);
            }
            uint32_t bhi[8][2], blo[8][2];
#pragma unroll
            for (int g = 0; g < 4; g++) {
                uint32_t bd = tile + T_B_HI + b_lm_off + g * (16 * PITCH) + koff;
                ldmatrix_x4(bhi[g*2][0], bhi[g*2][1], bhi[g*2+1][0], bhi[g*2+1][1], bd);
                bd = tile + T_B_LO + b_lm_off + g * (16 * PITCH) + koff;
                ldmatrix_x4(blo[g*2][0], blo[g*2][1], blo[g*2+1][0], blo[g*2+1][1], bd);
            }
#pragma unroll
            for (int mf = 0; mf < 2; mf++)
#pragma unroll
                for (int nf = 0; nf < 8; nf++) {
                    mma_bf16(acc[mf][nf], ahi[mf], bhi[nf]);
                    mma_bf16(acc[mf][nf], ahi[mf], blo[nf]);
                    mma_bf16(acc[mf][nf], alo[mf], bhi[nf]);
                }
        }

        // convert + store next stage
        if (s + 1 < S) {
            char* stg = smem + (cur ^ 1) * STAGE_B;
#pragma unroll
            for (int q = 0; q < 4; q++) {
                uint32_t h0 = bf16x2_rn(av[q].x, av[q].y);
                uint32_t h1 = bf16x2_rn(av[q].z, av[q].w);
                uint32_t l0 = bf16x2_rn(av[q].x - bf16lo_to_f(h0), av[q].y - bf16hi_to_f(h0));
                uint32_t l1 = bf16x2_rn(av[q].z - bf16lo_to_f(h1), av[q].w - bf16hi_to_f(h1));
                *(uint2*)(stg + T_A_HI + sts_off + q * 8) = make_uint2(h0, h1);
                *(uint2*)(stg + T_A_LO + sts_off + q * 8) = make_uint2(l0, l1);
                uint32_t g0 = bf16x2_rn(bv[q].x, bv[q].y);
                uint32_t g1 = bf16x2_rn(bv[q].z, bv[q].w);
                uint32_t m0 = bf16x2_rn(bv[q].x - bf16lo_to_f(g0), bv[q].y - bf16hi_to_f(g0));
                uint32_t m1 = bf16x2_rn(bv[q].z - bf16lo_to_f(g1), bv[q].w - bf16hi_to_f(g1));
                *(uint2*)(stg + T_B_HI + sts_off + q * 8) = make_uint2(g0, g1);
                *(uint2*)(stg + T_B_LO + sts_off + q * 8) = make_uint2(m0, m1);
            }
        }
        __syncthreads();
    }

    // epilogue: bias + SELU, direct STG
    int tig = lid & 3, grp = lid >> 2;
#pragma unroll
    for (int nf = 0; nf < 8; nf++) {
        int col = bn + warp_n * 64 + nf * 8 + tig * 2;
        float bz0 = bias[col], bz1 = bias[col + 1];
#pragma unroll
        for (int mf = 0; mf < 2; mf++) {
            int row0 = bm + warp_m * 32 + mf * 16 + grp;
            if (row0 < M) {
                float2 o;
                o.x = selu_f(acc[mf][nf][0] + bz0);
                o.y = selu_f(acc[mf][nf][1] + bz1);
                *(float2*)(C + (size_t)row0 * F_W + col) = o;
            }
            if (row0 + 8 < M) {
                float2 o;
                o.x = selu_f(acc[mf][nf][2] + bz0);
                o.y = selu_f(acc[mf][nf][3] + bz1);
                *(float2*)(C + (size_t)(row0 + 8) * F_W + col) = o;
            }
        }
    }
}

// ---------------- launch ----------------
extern "C" void kernel_launch(void* const* d_in, const int* in_sizes, int n_in,
                              void* d_out, int out_size) {
    const float* v      = (const float*)d_in[0];
    const float* e_rel  = (const float*)d_in[1];
    const void*  idx    = (const void*) d_in[2];
    const float* v_skip = (const float*)d_in[3];
    const float* We     = (const float*)d_in[4];
    const float* be     = (const float*)d_in[5];
    const float* ln_g   = (const float*)d_in[6];
    const float* ln_b   = (const float*)d_in[7];
    const float* W0     = (const float*)d_in[8];
    const float* b0     = (const float*)d_in[9];
    const float* W1     = (const float*)d_in[10];
    const float* b1     = (const float*)d_in[11];
    const float* W2     = (const float*)d_in[12];
    const float* b2     = (const float*)d_in[13];
    const float* W3     = (const float*)d_in[14];
    const float* b3     = (const float*)d_in[15];

    int M = in_sizes[1];  // e_rel element count = N_HR

    float *msg, *h0, *h1;
    cudaGetSymbolAddress((void**)&msg, g_msg);
    cudaGetSymbolAddress((void**)&h0,  g_h0);
    cudaGetSymbolAddress((void**)&h1,  g_h1);

    cudaFuncSetAttribute(gemm_bf16x3_selu,
                         cudaFuncAttributeMaxDynamicSharedMemorySize, GEMM_SMEM);

    detect_idx_kernel<<<1, 1>>>((const int*)idx);
    prep_kernel<<<M, 256>>>(v, e_rel, idx, v_skip, We, be, ln_g, ln_b, M);

    dim3 grid(F_W / BN, (M + BM - 1) / BM);
    gemm_bf16x3_selu<<<grid, 256, GEMM_SMEM>>>(msg, W0, b0, h0, M, IN_MSG);
    gemm_bf16x3_selu<<<grid, 256, GEMM_SMEM>>>(h0,  W1, b1, h1, M, F_W);
    gemm_bf16x3_selu<<<grid, 256, GEMM_SMEM>>>(h1,  W2, b2, h0, M, F_W);
    gemm_bf16x3_selu<<<grid, 256, GEMM_SMEM>>>(h0,  W3, b3, (float*)d_out, M, F_W);
}